// round 13
// baseline (speedup 1.0000x reference)
#include <cuda_runtime.h>
#include <cuda_fp16.h>
#include <float.h>

// features: [B=8, X=128, Y=128, C=128] f32   (C contiguous)
// rois:     [B, N=128, 4] i32  (minX, minY, maxX, maxY)
// out:      [B, N, 7, 7, C] f32
//
// Two-pass pyramid with FP16 intermediate:
//   Pass 1: P1[b][x][y][c] = (half)max 2x2 window of features
//   Pass 2: bin (>=2x2) = max over P1 at stride-2 samples clamped to edge-2,
//           half2 accumulate. Grid-strided: each block processes STRIPS_PB
//           (b,n,h) strips (warp w -> bin w), amortizing CTA launch overhead.

#define PH 7
#define PW 7
#define B_ 8
#define N_ 128
#define XDIM 128
#define YDIM 128
#define C4   32                  // 32 channel-quarters per pixel (4 ch each)
#define COLS (YDIM * C4)         // stride (in quarters) for +1 in x (4096)

// 32 MB scratch: [b][x][y][c4] half4 stored as uint2
__device__ uint2 d_P1[B_ * XDIM * YDIM * C4];

__device__ __forceinline__ float4 f4max(float4 a, float4 b) {
    return make_float4(fmaxf(a.x, b.x), fmaxf(a.y, b.y),
                       fmaxf(a.z, b.z), fmaxf(a.w, b.w));
}

__device__ __forceinline__ uint2 f4_to_h4(float4 v) {
    __half2 h01 = __floats2half2_rn(v.x, v.y);
    __half2 h23 = __floats2half2_rn(v.z, v.w);
    uint2 u;
    u.x = *reinterpret_cast<unsigned*>(&h01);
    u.y = *reinterpret_cast<unsigned*>(&h23);
    return u;
}

// ---------------- Pass 1: sliding 2x2 max -> fp16 (unchanged) ----------------
#define P1_XR 4
#define P1_YS 4
#define P1_WPB 8

__global__ __launch_bounds__(P1_WPB * 32)
void build_p1_kernel(const float4* __restrict__ f)
{
    int gw   = blockIdx.x * P1_WPB + (threadIdx.x >> 5);
    int lane = threadIdx.x & 31;

    int yc = gw & 31;            // 32 y-chunks of 4
    int t  = gw >> 5;
    int xg = t & 31;             // 32 x-groups of 4
    int b  = t >> 5;
    int y0 = yc * P1_YS;
    int x0 = xg * P1_XR;

    const float4* p0 = f + (b * XDIM + x0) * COLS + y0 * C4 + lane;
    const float4* p1 = p0 + COLS;
    const float4* p2 = p1 + COLS;
    const float4* p3 = p2 + COLS;
    // row x0+4 clamped to 127 (only xg==31; junk output never read by pass 2)
    const float4* p4 = f + (b * XDIM + min(x0 + 4, XDIM - 1)) * COLS + y0 * C4 + lane;

    uint2* o = d_P1 + (b * XDIM + x0) * COLS + y0 * C4 + lane;

    int ymax = (YDIM - 1) - y0;  // clamp next-row load offset to y=127

    float4 c0 = p0[0], c1 = p1[0], c2 = p2[0], c3 = p3[0], c4 = p4[0];

    #pragma unroll
    for (int i = 0; i < P1_YS; ++i) {
        int off = min(i + 1, ymax) * C4;
        float4 n0 = p0[off];
        float4 n1 = p1[off];
        float4 n2 = p2[off];
        float4 n3 = p3[off];
        float4 n4 = p4[off];
        o[0 * COLS + i * C4] = f4_to_h4(f4max(f4max(c0, c1), f4max(n0, n1)));
        o[1 * COLS + i * C4] = f4_to_h4(f4max(f4max(c1, c2), f4max(n1, n2)));
        o[2 * COLS + i * C4] = f4_to_h4(f4max(f4max(c2, c3), f4max(n2, n3)));
        o[3 * COLS + i * C4] = f4_to_h4(f4max(f4max(c3, c4), f4max(n3, n4)));
        c0 = n0; c1 = n1; c2 = n2; c3 = n3; c4 = n4;
    }
}

// ---------------- Pass 2: ROI pooling from fp16 P1, grid-strided ------------
__device__ __forceinline__ void h4acc(uint2 v, __half2& a, __half2& b) {
    a = __hmax2(a, *reinterpret_cast<__half2*>(&v.x));
    b = __hmax2(b, *reinterpret_cast<__half2*>(&v.y));
}

#define P2_STRIPS (B_ * N_ * PH)     // 7168
#define P2_SPB    4                   // strips per block
#define P2_GRID   (P2_STRIPS / P2_SPB)

__global__ __launch_bounds__(PW * 32, 7)
void roi_pool_p1_kernel(const int4* __restrict__ rois,
                        float4*     __restrict__ out)
{
    int w    = threadIdx.x >> 5;
    int lane = threadIdx.x & 31;
    // reversed base so freshest P1 batches (written last by pass 1) come first
    int bid0 = (P2_STRIPS - 1) - blockIdx.x * P2_SPB;

    #pragma unroll 1
    for (int s = 0; s < P2_SPB; ++s) {
        int bid = bid0 - s;           // strip id = t*PH + h
        int h   = bid % PH;
        int t   = bid / PH;           // t = b*N_ + n
        int b   = t >> 7;             // / N_

        const int4 r = rois[t];
        int dx = (r.z - r.x) / PW;
        int dy = (r.w - r.y) / PH;

        int y0 = r.y + h * dy;
        int ny = (h == PH - 1) ? (r.w - y0) : dy;    // >= 2
        int x0 = r.x + w * dx;
        int nx = (w == PW - 1) ? (r.z - x0) : dx;    // >= 2

        int cx = (nx + 1) >> 1;
        int cy = (ny + 1) >> 1;
        int xle = (nx - 2) * COLS;    // clamp: last x sample = x1-2
        int yle = (ny - 2) * C4;      // clamp: last y sample = y1-2

        const uint2* base = d_P1 + (b * XDIM + x0) * COLS + y0 * C4 + lane;

        const __half2 NEG = __float2half2_rn(-65504.0f);
        __half2 m0 = NEG, m1 = NEG;
        __half2 m2 = NEG, m3 = NEG;

        int j = 0;
        for (; j + 2 <= cx; j += 2) {                 // two sample-columns
            const uint2* pA = base + min(2 * j * COLS, xle);
            const uint2* pB = base + min((2 * j + 2) * COLS, xle);
            int i = 0;
            for (; i + 2 <= cy; i += 2) {
                uint2 a0 = pA[min(2 * i * C4, yle)];
                uint2 a1 = pA[min((2 * i + 2) * C4, yle)];
                uint2 b0 = pB[min(2 * i * C4, yle)];
                uint2 b1 = pB[min((2 * i + 2) * C4, yle)];
                h4acc(a0, m0, m1);
                h4acc(a1, m2, m3);
                h4acc(b0, m0, m1);
                h4acc(b1, m2, m3);
            }
            if (i < cy) {
                int yo = min(2 * i * C4, yle);
                h4acc(pA[yo], m0, m1);
                h4acc(pB[yo], m2, m3);
            }
        }
        if (j < cx) {                                  // last single column
            const uint2* pA = base + min(2 * j * COLS, xle);
            int i = 0;
            for (; i + 2 <= cy; i += 2) {
                uint2 a0 = pA[min(2 * i * C4, yle)];
                uint2 a1 = pA[min((2 * i + 2) * C4, yle)];
                h4acc(a0, m0, m1);
                h4acc(a1, m2, m3);
            }
            if (i < cy) {
                h4acc(pA[min(2 * i * C4, yle)], m0, m1);
            }
        }

        __half2 r01 = __hmax2(m0, m2);
        __half2 r23 = __hmax2(m1, m3);
        float2 lo = __half22float2(r01);
        float2 hi = __half22float2(r23);
        out[(bid * PW + w) * C4 + lane] = make_float4(lo.x, lo.y, hi.x, hi.y);
    }
}

extern "C" void kernel_launch(void* const* d_in, const int* in_sizes, int n_in,
                              void* d_out, int out_size)
{
    const float4* features = (const float4*)d_in[0];
    const int4*   rois     = (const int4*)d_in[1];
    float4*       out      = (float4*)d_out;

    // Pass 1: 8*32*32 = 8192 warps -> 1024 blocks of 8 warps
    dim3 grid1(B_ * 32 * 32 / P1_WPB);
    dim3 block1(P1_WPB * 32);
    build_p1_kernel<<<grid1, block1>>>(features);

    // Pass 2: 1792 blocks x 224, 4 strips per block
    dim3 grid2(P2_GRID);
    dim3 block2(PW * 32);
    roi_pool_p1_kernel<<<grid2, block2>>>(rois, out);
}

// round 14
// speedup vs baseline: 1.0483x; 1.0483x over previous
#include <cuda_runtime.h>
#include <cuda_fp16.h>
#include <float.h>

// features: [B=8, X=128, Y=128, C=128] f32   (C contiguous)
// rois:     [B, N=128, 4] i32  (minX, minY, maxX, maxY)
// out:      [B, N, 7, 7, C] f32
//
// Two-pass pyramid with FP16 intermediate:
//   Pass 1: P1[b][x][y][c] = (half)max 2x2 window; 8x8 output tiles from
//           9x9 inputs (1.27x read amplification vs 1.56x for 4x4 tiles).
//   Pass 2 (R12 exact, verified 22.4us): bin = max over P1 stride-2 samples
//           clamped to edge-2, half2 accumulate, reversed block order.

#define PH 7
#define PW 7
#define B_ 8
#define N_ 128
#define XDIM 128
#define YDIM 128
#define C4   32                  // 32 channel-quarters per pixel (4 ch each)
#define COLS (YDIM * C4)         // stride (in quarters) for +1 in x (4096)

// 32 MB scratch: [b][x][y][c4] half4 stored as uint2
__device__ uint2 d_P1[B_ * XDIM * YDIM * C4];

__device__ __forceinline__ float4 f4max(float4 a, float4 b) {
    return make_float4(fmaxf(a.x, b.x), fmaxf(a.y, b.y),
                       fmaxf(a.z, b.z), fmaxf(a.w, b.w));
}

__device__ __forceinline__ uint2 f4_to_h4(float4 v) {
    __half2 h01 = __floats2half2_rn(v.x, v.y);
    __half2 h23 = __floats2half2_rn(v.z, v.w);
    uint2 u;
    u.x = *reinterpret_cast<unsigned*>(&h01);
    u.y = *reinterpret_cast<unsigned*>(&h23);
    return u;
}

// ---------------- Pass 1: sliding 2x2 max -> fp16, 8x8 tiles ----------------
// warp -> (b, xg, yc): outputs x in [8*xg,8*xg+8), y in [8*yc,8*yc+8).
// Carries 9 rows in registers; 9 loads per y-step. 2048 warps.
#define P1_XR 8
#define P1_YS 8
#define P1_WPB 8

__global__ __launch_bounds__(P1_WPB * 32)
void build_p1_kernel(const float4* __restrict__ f)
{
    int gw   = blockIdx.x * P1_WPB + (threadIdx.x >> 5);
    int lane = threadIdx.x & 31;

    int yc = gw & 15;            // 16 y-chunks of 8
    int t  = gw >> 4;
    int xg = t & 15;             // 16 x-groups of 8
    int b  = t >> 4;
    int y0 = yc * P1_YS;
    int x0 = xg * P1_XR;

    // 9 row pointers; row x0+8 clamped to 127 (only xg==15; that junk output
    // row 127 is never read by pass 2: samples need x <= maxX-2 <= 125)
    const float4* p[P1_XR + 1];
    #pragma unroll
    for (int k = 0; k <= P1_XR; ++k)
        p[k] = f + (b * XDIM + min(x0 + k, XDIM - 1)) * COLS + y0 * C4 + lane;

    uint2* o = d_P1 + (b * XDIM + x0) * COLS + y0 * C4 + lane;

    int ymax = (YDIM - 1) - y0;  // clamp next-row load offset to y=127

    float4 c[P1_XR + 1];
    #pragma unroll
    for (int k = 0; k <= P1_XR; ++k)
        c[k] = p[k][0];

    #pragma unroll
    for (int i = 0; i < P1_YS; ++i) {
        int off = min(i + 1, ymax) * C4;
        float4 n[P1_XR + 1];
        #pragma unroll
        for (int k = 0; k <= P1_XR; ++k)
            n[k] = p[k][off];
        #pragma unroll
        for (int k = 0; k < P1_XR; ++k)
            o[k * COLS + i * C4] =
                f4_to_h4(f4max(f4max(c[k], c[k + 1]), f4max(n[k], n[k + 1])));
        #pragma unroll
        for (int k = 0; k <= P1_XR; ++k)
            c[k] = n[k];
    }
}

// ---------------- Pass 2: ROI pooling from fp16 P1 (R12 exact) --------------
__device__ __forceinline__ void h4acc(uint2 v, __half2& a, __half2& b) {
    a = __hmax2(a, *reinterpret_cast<__half2*>(&v.x));
    b = __hmax2(b, *reinterpret_cast<__half2*>(&v.y));
}

__global__ __launch_bounds__(PW * 32, 6)
void roi_pool_p1_kernel(const int4* __restrict__ rois,
                        float4*     __restrict__ out)
{
    int bid  = (int)gridDim.x - 1 - blockIdx.x;   // reversed: b=7 first (L2-hot P1)
    int h    = bid % PH;
    int t    = bid / PH;          // t = b*N_ + n
    int b    = t >> 7;            // / N_
    int w    = threadIdx.x >> 5;
    int lane = threadIdx.x & 31;

    const int4 r = rois[t];
    int dx = (r.z - r.x) / PW;
    int dy = (r.w - r.y) / PH;

    int y0 = r.y + h * dy;
    int ny = (h == PH - 1) ? (r.w - y0) : dy;    // >= 2
    int x0 = r.x + w * dx;
    int nx = (w == PW - 1) ? (r.z - x0) : dx;    // >= 2

    int cx = (nx + 1) >> 1;
    int cy = (ny + 1) >> 1;
    int xle = (nx - 2) * COLS;    // clamp: last x sample = x1-2
    int yle = (ny - 2) * C4;      // clamp: last y sample = y1-2

    const uint2* base = d_P1 + (b * XDIM + x0) * COLS + y0 * C4 + lane;

    const __half2 NEG = __float2half2_rn(-65504.0f);
    __half2 m0 = NEG, m1 = NEG;
    __half2 m2 = NEG, m3 = NEG;

    int j = 0;
    for (; j + 2 <= cx; j += 2) {                 // two sample-columns at once
        const uint2* pA = base + min(2 * j * COLS, xle);
        const uint2* pB = base + min((2 * j + 2) * COLS, xle);
        int i = 0;
        for (; i + 2 <= cy; i += 2) {
            uint2 a0 = pA[min(2 * i * C4, yle)];
            uint2 a1 = pA[min((2 * i + 2) * C4, yle)];
            uint2 b0 = pB[min(2 * i * C4, yle)];
            uint2 b1 = pB[min((2 * i + 2) * C4, yle)];
            h4acc(a0, m0, m1);
            h4acc(a1, m2, m3);
            h4acc(b0, m0, m1);
            h4acc(b1, m2, m3);
        }
        if (i < cy) {
            int yo = min(2 * i * C4, yle);
            h4acc(pA[yo], m0, m1);
            h4acc(pB[yo], m2, m3);
        }
    }
    if (j < cx) {                                  // last single sample-column
        const uint2* pA = base + min(2 * j * COLS, xle);
        int i = 0;
        for (; i + 2 <= cy; i += 2) {
            uint2 a0 = pA[min(2 * i * C4, yle)];
            uint2 a1 = pA[min((2 * i + 2) * C4, yle)];
            h4acc(a0, m0, m1);
            h4acc(a1, m2, m3);
        }
        if (i < cy) {
            h4acc(pA[min(2 * i * C4, yle)], m0, m1);
        }
    }

    __half2 r01 = __hmax2(m0, m2);
    __half2 r23 = __hmax2(m1, m3);
    float2 lo = __half22float2(r01);
    float2 hi = __half22float2(r23);
    out[(bid * PW + w) * C4 + lane] = make_float4(lo.x, lo.y, hi.x, hi.y);
}

extern "C" void kernel_launch(void* const* d_in, const int* in_sizes, int n_in,
                              void* d_out, int out_size)
{
    const float4* features = (const float4*)d_in[0];
    const int4*   rois     = (const int4*)d_in[1];
    float4*       out      = (float4*)d_out;

    // Pass 1: 8*16*16 = 2048 warps -> 256 blocks of 8 warps
    dim3 grid1(B_ * 16 * 16 / P1_WPB);
    dim3 block1(P1_WPB * 32);
    build_p1_kernel<<<grid1, block1>>>(features);

    // Pass 2
    dim3 grid2(B_ * N_ * PH);                      // 7168
    dim3 block2(PW * 32);                          // 224
    roi_pool_p1_kernel<<<grid2, block2>>>(rois, out);
}

// round 15
// speedup vs baseline: 1.1372x; 1.0848x over previous
#include <cuda_runtime.h>
#include <cuda_fp16.h>
#include <float.h>

// features: [B=8, X=128, Y=128, C=128] f32   (C contiguous)
// rois:     [B, N=128, 4] i32  (minX, minY, maxX, maxY)
// out:      [B, N, 7, 7, C] f32
//
// FUSED persistent kernel:
//   Stage 1: P1[b][x][y][c] = (half)max 2x2 window of features (4x4 tiles,
//            register-carried rows), grid-strided over 8192 warp-tiles.
//   ---- software grid barrier (all CTAs co-resident by construction) ----
//   Stage 2: bin (>=2x2 guaranteed) = max over P1 at stride-2 samples
//            clamped to edge-2, half2 accumulate (R12-verified inner loop),
//            grid-strided over 50176 warp-bins.

#define PH 7
#define PW 7
#define B_ 8
#define N_ 128
#define XDIM 128
#define YDIM 128
#define C4   32                  // 32 channel-quarters per pixel (4 ch each)
#define COLS (YDIM * C4)         // stride (in quarters) for +1 in x (4096)

#define NBLOCKS 296              // 148 SMs x 2 co-resident CTAs
#define NTHREADS 512
#define NWARPS (NBLOCKS * (NTHREADS / 32))   // 4736

#define P1_TILES (B_ * 32 * 32)              // 8192 warp-tiles (4x4 each)
#define P2_BINS  (B_ * N_ * PH * PW)         // 50176 warp-bins

// 32 MB scratch: [b][x][y][c4] half4 stored as uint2
__device__ uint2 d_P1[B_ * XDIM * YDIM * C4];
__device__ unsigned d_bar;

__device__ __forceinline__ float4 f4max(float4 a, float4 b) {
    return make_float4(fmaxf(a.x, b.x), fmaxf(a.y, b.y),
                       fmaxf(a.z, b.z), fmaxf(a.w, b.w));
}

__device__ __forceinline__ uint2 f4_to_h4(float4 v) {
    __half2 h01 = __floats2half2_rn(v.x, v.y);
    __half2 h23 = __floats2half2_rn(v.z, v.w);
    uint2 u;
    u.x = *reinterpret_cast<unsigned*>(&h01);
    u.y = *reinterpret_cast<unsigned*>(&h23);
    return u;
}

__device__ __forceinline__ void h4acc(uint2 v, __half2& a, __half2& b) {
    a = __hmax2(a, *reinterpret_cast<__half2*>(&v.x));
    b = __hmax2(b, *reinterpret_cast<__half2*>(&v.y));
}

// ---------------- Stage 1 tile: 4x4 outputs from 5x5 inputs ----------------
__device__ __forceinline__ void p1_tile(const float4* __restrict__ f, int tile,
                                        int lane)
{
    int yc = tile & 31;          // 32 y-chunks of 4
    int t  = tile >> 5;
    int xg = t & 31;             // 32 x-groups of 4
    int b  = t >> 5;
    int y0 = yc * 4;
    int x0 = xg * 4;

    const float4* p0 = f + (b * XDIM + x0) * COLS + y0 * C4 + lane;
    const float4* p1 = p0 + COLS;
    const float4* p2 = p1 + COLS;
    const float4* p3 = p2 + COLS;
    // row x0+4 clamped to 127 (only xg==31; junk output never read by stage 2)
    const float4* p4 = f + (b * XDIM + min(x0 + 4, XDIM - 1)) * COLS + y0 * C4 + lane;

    uint2* o = d_P1 + (b * XDIM + x0) * COLS + y0 * C4 + lane;

    int ymax = (YDIM - 1) - y0;  // clamp next-row load offset to y=127

    float4 c0 = p0[0], c1 = p1[0], c2 = p2[0], c3 = p3[0], c4 = p4[0];

    #pragma unroll
    for (int i = 0; i < 4; ++i) {
        int off = min(i + 1, ymax) * C4;
        float4 n0 = p0[off];
        float4 n1 = p1[off];
        float4 n2 = p2[off];
        float4 n3 = p3[off];
        float4 n4 = p4[off];
        o[0 * COLS + i * C4] = f4_to_h4(f4max(f4max(c0, c1), f4max(n0, n1)));
        o[1 * COLS + i * C4] = f4_to_h4(f4max(f4max(c1, c2), f4max(n1, n2)));
        o[2 * COLS + i * C4] = f4_to_h4(f4max(f4max(c2, c3), f4max(n2, n3)));
        o[3 * COLS + i * C4] = f4_to_h4(f4max(f4max(c3, c4), f4max(n3, n4)));
        c0 = n0; c1 = n1; c2 = n2; c3 = n3; c4 = n4;
    }
}

// ---------------- Stage 2 bin: R12-verified inner loop ----------------
__device__ __forceinline__ void p2_bin(const int4* __restrict__ rois, int u,
                                       int lane, float4* __restrict__ out)
{
    int w = u % PW;
    int s = u / PW;
    int h = s % PH;
    int t = s / PH;               // t = b*N_ + n
    int b = t >> 7;               // / N_

    const int4 r = rois[t];
    int dx = (r.z - r.x) / PW;
    int dy = (r.w - r.y) / PH;

    int y0 = r.y + h * dy;
    int ny = (h == PH - 1) ? (r.w - y0) : dy;    // >= 2
    int x0 = r.x + w * dx;
    int nx = (w == PW - 1) ? (r.z - x0) : dx;    // >= 2

    int cx = (nx + 1) >> 1;
    int cy = (ny + 1) >> 1;
    int xle = (nx - 2) * COLS;    // clamp: last x sample = x1-2
    int yle = (ny - 2) * C4;      // clamp: last y sample = y1-2

    const uint2* base = d_P1 + (b * XDIM + x0) * COLS + y0 * C4 + lane;

    const __half2 NEG = __float2half2_rn(-65504.0f);
    __half2 m0 = NEG, m1 = NEG;
    __half2 m2 = NEG, m3 = NEG;

    int j = 0;
    for (; j + 2 <= cx; j += 2) {                 // two sample-columns at once
        const uint2* pA = base + min(2 * j * COLS, xle);
        const uint2* pB = base + min((2 * j + 2) * COLS, xle);
        int i = 0;
        for (; i + 2 <= cy; i += 2) {
            uint2 a0 = pA[min(2 * i * C4, yle)];
            uint2 a1 = pA[min((2 * i + 2) * C4, yle)];
            uint2 b0 = pB[min(2 * i * C4, yle)];
            uint2 b1 = pB[min((2 * i + 2) * C4, yle)];
            h4acc(a0, m0, m1);
            h4acc(a1, m2, m3);
            h4acc(b0, m0, m1);
            h4acc(b1, m2, m3);
        }
        if (i < cy) {
            int yo = min(2 * i * C4, yle);
            h4acc(pA[yo], m0, m1);
            h4acc(pB[yo], m2, m3);
        }
    }
    if (j < cx) {                                  // last single sample-column
        const uint2* pA = base + min(2 * j * COLS, xle);
        int i = 0;
        for (; i + 2 <= cy; i += 2) {
            uint2 a0 = pA[min(2 * i * C4, yle)];
            uint2 a1 = pA[min((2 * i + 2) * C4, yle)];
            h4acc(a0, m0, m1);
            h4acc(a1, m2, m3);
        }
        if (i < cy) {
            h4acc(pA[min(2 * i * C4, yle)], m0, m1);
        }
    }

    __half2 r01 = __hmax2(m0, m2);
    __half2 r23 = __hmax2(m1, m3);
    float2 lo = __half22float2(r01);
    float2 hi = __half22float2(r23);
    out[u * C4 + lane] = make_float4(lo.x, lo.y, hi.x, hi.y);
}

// ---------------- fused persistent kernel ----------------
__global__ __launch_bounds__(NTHREADS, 2)
void roi_fused_kernel(const float4* __restrict__ features,
                      const int4*   __restrict__ rois,
                      float4*       __restrict__ out)
{
    int wid  = threadIdx.x >> 5;
    int lane = threadIdx.x & 31;
    int gwarp = blockIdx.x * (NTHREADS / 32) + wid;

    // ---- Stage 1: build P1 ----
    for (int tile = gwarp; tile < P1_TILES; tile += NWARPS)
        p1_tile(features, tile, lane);

    // ---- grid barrier (all NBLOCKS CTAs co-resident: 2 per SM guaranteed) ----
    __threadfence();              // make P1 stores visible GPU-wide
    __syncthreads();
    if (threadIdx.x == 0) {
        atomicAdd(&d_bar, 1u);
        while (atomicAdd(&d_bar, 0u) < (unsigned)gridDim.x)
            __nanosleep(64);
    }
    __syncthreads();
    __threadfence();              // order P1 loads after the barrier

    // ---- Stage 2: pool bins from P1 ----
    for (int u = gwarp; u < P2_BINS; u += NWARPS)
        p2_bin(rois, u, lane, out);
}

extern "C" void kernel_launch(void* const* d_in, const int* in_sizes, int n_in,
                              void* d_out, int out_size)
{
    const float4* features = (const float4*)d_in[0];
    const int4*   rois     = (const int4*)d_in[1];
    float4*       out      = (float4*)d_out;

    // zero the barrier counter (capturable async memset, no allocation)
    void* bar_ptr = nullptr;
    cudaGetSymbolAddress(&bar_ptr, d_bar);
    cudaMemsetAsync(bar_ptr, 0, sizeof(unsigned));

    roi_fused_kernel<<<NBLOCKS, NTHREADS>>>(features, rois, out);
}